// round 2
// baseline (speedup 1.0000x reference)
#include <cuda_runtime.h>
#include <cuda_bf16.h>

// Problem constants
#define BN_ 2
#define T_ 8
#define BT 16          // b*t
#define C_ 64          // dim
#define HID 128
#define H_ 128
#define W_ 128
#define P 16384        // H*W

// ---------------- scratch (device globals; no runtime allocation) ------------
__device__ float g_xn[BT * C_ * P];          // layernormed x, [bt][c][p]
__device__ float g_x1[BT * HID * P];         // pin output ch 0..127, [bt][ch][p] (== x1r)
__device__ float g_x2[BT * HID * P];         // pin output ch 128..255, [bt][ch][p]
__device__ float g_gated[BT * HID * P];      // (dyn dwconv + bias) * x2
__device__ float g_pooled[BT * HID];         // pooled (16,128)
__device__ float g_kern[BT * HID * 9];       // dynamic kernels (16,1152)
__device__ float g_pinT[3 * 64 * 256];       // pin_w transposed: [(dt*64+c)*256 + n]
__device__ float g_poutT[3 * 128 * 64];      // pout_w transposed: [(dt*128+c)*64 + n]

// ---------------- K0: weight transpose (coalesced GEMM B-operands) -----------
__global__ void __launch_bounds__(256) transpose_w(const float* __restrict__ pin,
                                                   const float* __restrict__ pout) {
    int i = blockIdx.x * 256 + threadIdx.x;
    if (i < 3 * 64 * 256) {
        int n = i & 255;
        int cd = i >> 8;           // dt*64 + c
        int c = cd & 63;
        int dt = cd >> 6;
        g_pinT[i] = pin[(n * 64 + c) * 3 + dt];
    }
    if (i < 3 * 128 * 64) {
        int n = i & 63;
        int cd = i >> 6;           // dt*128 + ch
        int ch = cd & 127;
        int dt = cd >> 7;
        g_poutT[i] = pout[(n * 128 + ch) * 3 + dt];
    }
}

// ---------------- K1: LayerNorm over channel dim per pixel -------------------
__global__ void __launch_bounds__(256) ln_kernel(const float* __restrict__ x,
                                                 const float* __restrict__ lw,
                                                 const float* __restrict__ lb) {
    int p = blockIdx.x * 256 + threadIdx.x;
    int bt = blockIdx.y;
    const float* xp = x + bt * C_ * P + p;
    float v[64];
    float sum = 0.f;
#pragma unroll
    for (int c = 0; c < 64; c++) { v[c] = xp[c * P]; sum += v[c]; }
    float mu = sum * (1.f / 64.f);
    float var = 0.f;
#pragma unroll
    for (int c = 0; c < 64; c++) { float d = v[c] - mu; var += d * d; }
    float rs = rsqrtf(var * (1.f / 64.f) + 1e-5f);
    float* op = g_xn + bt * C_ * P + p;
#pragma unroll
    for (int c = 0; c < 64; c++) op[c * P] = (v[c] - mu) * rs * lw[c] + lb[c];
}

// ---------------- K2: pin conv3d as GEMM (M=P per bt, N=256, K=192) ----------
// BM=128, BN=128, BK=16, 256 thr, 8x8 per thread. K-tile = single time tap.
__global__ void __launch_bounds__(256) pin_gemm() {
    const int bt = blockIdx.z;
    const int t = bt & 7;
    const int p0 = blockIdx.x * 128;
    const int n0 = blockIdx.y * 128;
    __shared__ float As[16][128];
    __shared__ float Ws[16][128];
    float acc[8][8];
#pragma unroll
    for (int i = 0; i < 8; i++)
#pragma unroll
        for (int j = 0; j < 8; j++) acc[i][j] = 0.f;
    const int tid = threadIdx.x;
    const int pg = (tid & 15) * 8;
    const int ng = (tid >> 4) * 8;
    const int lp = tid & 127;
    const int lk = tid >> 7;  // 0/1
    for (int kt = 0; kt < 12; kt++) {
        const int dt = kt >> 2;            // k0/64
        const int c0 = (kt & 3) * 16;
        const int ts = t + dt - 1;
        if (ts < 0 || ts > 7) continue;    // zero-pad tap: skip whole tile (uniform)
        const float* ab = g_xn + ((bt + dt - 1) * 64 + c0) * P + p0;
        const float* wb = g_pinT + (dt * 64 + c0) * 256 + n0;
#pragma unroll
        for (int i = 0; i < 8; i++) {
            As[lk + 2 * i][lp] = ab[(lk + 2 * i) * P + lp];
            Ws[lk + 2 * i][lp] = wb[(lk + 2 * i) * 256 + lp];
        }
        __syncthreads();
#pragma unroll
        for (int kk = 0; kk < 16; kk++) {
            float a[8], w[8];
#pragma unroll
            for (int i = 0; i < 8; i++) a[i] = As[kk][pg + i];
#pragma unroll
            for (int j = 0; j < 8; j++) w[j] = Ws[kk][ng + j];
#pragma unroll
            for (int i = 0; i < 8; i++)
#pragma unroll
                for (int j = 0; j < 8; j++) acc[i][j] += a[i] * w[j];
        }
        __syncthreads();
    }
    float* dst0 = (n0 == 0) ? (g_x1 + bt * 128 * P) : (g_x2 + bt * 128 * P);
#pragma unroll
    for (int j = 0; j < 8; j++) {
        float* dst = dst0 + (ng + j) * P + p0 + pg;
#pragma unroll
        for (int i = 0; i < 8; i++) dst[i] = acc[i][j];
    }
}

// ---------------- K3: fused pooling branch, one block per (bt,ch) ------------
__global__ void __launch_bounds__(256) pool_branch(const float* __restrict__ b1w,
                                                   const float* __restrict__ b1b,
                                                   const float* __restrict__ b2w,
                                                   const float* __restrict__ b2b) {
    __shared__ float sA[4096];
    __shared__ float sB[4096];
    __shared__ float red[8];
    const int btc = blockIdx.x;       // bt*128 + ch
    const int ch = btc & 127;
    const int tid = threadIdx.x;
    const float* src = g_x1 + btc * P;

    // avgpool 128x128 -> 64x64 (float2 reads keep coalescing)
    for (int i = tid; i < 4096; i += 256) {
        int py = i >> 6, px = i & 63;
        float2 a = ((const float2*)(src + (py * 2) * 128))[px];
        float2 b = ((const float2*)(src + (py * 2 + 1) * 128))[px];
        sA[i] = 0.25f * (a.x + a.y + b.x + b.y);
    }
    __syncthreads();

    // 3x depthwise 3x3 @64x64 : sA -> sB -> sA -> sB
    for (int it = 0; it < 3; it++) {
        float w[9];
#pragma unroll
        for (int k = 0; k < 9; k++) w[k] = b1w[(it * 128 + ch) * 9 + k];
        float bias = b1b[it * 128 + ch];
        const float* in = (it & 1) ? sB : sA;
        float* out = (it & 1) ? sA : sB;
        for (int i = tid; i < 4096; i += 256) {
            int y = i >> 6, x = i & 63;
            float acc = bias;
#pragma unroll
            for (int ky = 0; ky < 3; ky++) {
                int yy = y + ky - 1;
                if (yy < 0 || yy > 63) continue;
#pragma unroll
                for (int kx = 0; kx < 3; kx++) {
                    int xx = x + kx - 1;
                    if (xx < 0 || xx > 63) continue;
                    acc += in[yy * 64 + xx] * w[ky * 3 + kx];
                }
            }
            out[i] = acc;
        }
        __syncthreads();
    }
    // result in sB; maxpool 64->32 into sA[0..1023]
    for (int i = tid; i < 1024; i += 256) {
        int py = i >> 5, px = i & 31;
        float m0 = fmaxf(sB[(py * 2) * 64 + px * 2], sB[(py * 2) * 64 + px * 2 + 1]);
        float m1 = fmaxf(sB[(py * 2 + 1) * 64 + px * 2], sB[(py * 2 + 1) * 64 + px * 2 + 1]);
        sA[i] = fmaxf(m0, m1);
    }
    __syncthreads();

    // 3x depthwise 3x3 @32x32 : sA -> sB -> sA -> sB
    for (int it = 0; it < 3; it++) {
        float w[9];
#pragma unroll
        for (int k = 0; k < 9; k++) w[k] = b2w[(it * 128 + ch) * 9 + k];
        float bias = b2b[it * 128 + ch];
        const float* in = (it & 1) ? sB : sA;
        float* out = (it & 1) ? sA : sB;
        for (int i = tid; i < 1024; i += 256) {
            int y = i >> 5, x = i & 31;
            float acc = bias;
#pragma unroll
            for (int ky = 0; ky < 3; ky++) {
                int yy = y + ky - 1;
                if (yy < 0 || yy > 31) continue;
#pragma unroll
                for (int kx = 0; kx < 3; kx++) {
                    int xx = x + kx - 1;
                    if (xx < 0 || xx > 31) continue;
                    acc += in[yy * 32 + xx] * w[ky * 3 + kx];
                }
            }
            out[i] = acc;
        }
        __syncthreads();
    }
    // result in sB[0..1023]; spatial mean
    float s = 0.f;
    for (int i = tid; i < 1024; i += 256) s += sB[i];
#pragma unroll
    for (int o = 16; o; o >>= 1) s += __shfl_xor_sync(0xFFFFFFFFu, s, o);
    if ((tid & 31) == 0) red[tid >> 5] = s;
    __syncthreads();
    if (tid == 0) {
        float tot = 0.f;
#pragma unroll
        for (int i = 0; i < 8; i++) tot += red[i];
        g_pooled[btc] = tot * (1.f / 1024.f);
    }
}

// ---------------- K4: kern = pooled @ tok_w.T + tok_b ------------------------
__global__ void __launch_bounds__(128) kern_gemm(const float* __restrict__ tw,
                                                 const float* __restrict__ tb) {
    __shared__ float sp[2048];
    int tid = threadIdx.x;
    for (int i = tid; i < 2048; i += 128) sp[i] = g_pooled[i];
    __syncthreads();
    int j = blockIdx.x * 128 + tid;  // 0..1151
    float acc[16];
#pragma unroll
    for (int b = 0; b < 16; b++) acc[b] = 0.f;
    const float4* wr = (const float4*)(tw + j * 128);
    for (int c4 = 0; c4 < 32; c4++) {
        float4 w = wr[c4];
#pragma unroll
        for (int b = 0; b < 16; b++) {
            const float* pp = sp + b * 128 + c4 * 4;
            acc[b] += w.x * pp[0] + w.y * pp[1] + w.z * pp[2] + w.w * pp[3];
        }
    }
    float bias = tb[j];
#pragma unroll
    for (int b = 0; b < 16; b++) g_kern[b * 1152 + j] = acc[b] + bias;
}

// ---------------- K5: dynamic depthwise conv + gate --------------------------
// one block per (bt,ch, half): 64 output rows + 1-row halo in smem
__global__ void __launch_bounds__(256) dyn_dw(const float* __restrict__ dwb) {
    __shared__ float s[66 * 128];
    const int btc = blockIdx.x;
    const int half = blockIdx.y;
    const int bt = btc >> 7, ch = btc & 127;
    const int r0 = half * 64;
    const int tid = threadIdx.x;
    const float* src = g_x1 + btc * P;
    for (int i = tid; i < 66 * 128; i += 256) {
        int rr = (i >> 7) + r0 - 1;
        s[i] = (rr >= 0 && rr < 128) ? src[rr * 128 + (i & 127)] : 0.f;
    }
    float kw[9];
#pragma unroll
    for (int k = 0; k < 9; k++) kw[k] = g_kern[bt * 1152 + ch * 9 + k];
    const float bias = dwb[ch];
    __syncthreads();
    const float* x2p = g_x2 + btc * P + r0 * 128;
    float* dst = g_gated + btc * P + r0 * 128;
    for (int i = tid; i < 64 * 128; i += 256) {
        int ly = (i >> 7) + 1;
        int x = i & 127;
        float acc = 0.f;
#pragma unroll
        for (int ky = 0; ky < 3; ky++) {
            const float* row = s + (ly + ky - 1) * 128;
            if (x > 0)   acc += row[x - 1] * kw[ky * 3];
                         acc += row[x]     * kw[ky * 3 + 1];
            if (x < 127) acc += row[x + 1] * kw[ky * 3 + 2];
        }
        dst[i] = (acc + bias) * x2p[i];
    }
}

// ---------------- K6: pout conv3d as GEMM + residual -------------------------
// BM=256, BN=64, BK=16, 256 thr, 8x8 per thread
__global__ void __launch_bounds__(256) pout_gemm(float* __restrict__ out,
                                                 const float* __restrict__ x) {
    const int bt = blockIdx.y;
    const int t = bt & 7;
    const int p0 = blockIdx.x * 256;
    __shared__ float As[16][256];
    __shared__ float Ws[16][64];
    float acc[8][8];
#pragma unroll
    for (int i = 0; i < 8; i++)
#pragma unroll
        for (int j = 0; j < 8; j++) acc[i][j] = 0.f;
    const int tid = threadIdx.x;
    const int pg = (tid & 31) * 8;
    const int ng = (tid >> 5) * 8;
    const int wn = tid & 63;
    const int wk = tid >> 6;  // 0..3
    for (int kt = 0; kt < 24; kt++) {
        const int dt = kt >> 3;            // k0/128
        const int c0 = (kt & 7) * 16;
        const int ts = t + dt - 1;
        if (ts < 0 || ts > 7) continue;
        const float* ab = g_gated + ((bt + dt - 1) * 128 + c0) * P + p0;
        const float* wb = g_poutT + (dt * 128 + c0) * 64;
#pragma unroll
        for (int i = 0; i < 16; i++) As[i][tid] = ab[i * P + tid];
#pragma unroll
        for (int i = 0; i < 4; i++) Ws[wk + 4 * i][wn] = wb[(wk + 4 * i) * 64 + wn];
        __syncthreads();
#pragma unroll
        for (int kk = 0; kk < 16; kk++) {
            float a[8], w[8];
#pragma unroll
            for (int i = 0; i < 8; i++) a[i] = As[kk][pg + i];
#pragma unroll
            for (int j = 0; j < 8; j++) w[j] = Ws[kk][ng + j];
#pragma unroll
            for (int i = 0; i < 8; i++)
#pragma unroll
                for (int j = 0; j < 8; j++) acc[i][j] += a[i] * w[j];
        }
        __syncthreads();
    }
#pragma unroll
    for (int j = 0; j < 8; j++) {
        int base = (bt * 64 + ng + j) * P + p0 + pg;
#pragma unroll
        for (int i = 0; i < 8; i++) out[base + i] = acc[i][j] + x[base + i];
    }
}

// ---------------- launch ------------------------------------------------------
extern "C" void kernel_launch(void* const* d_in, const int* in_sizes, int n_in,
                              void* d_out, int out_size) {
    (void)in_sizes; (void)n_in; (void)out_size;
    const float* x      = (const float*)d_in[0];
    const float* ln_w   = (const float*)d_in[1];
    const float* ln_b   = (const float*)d_in[2];
    const float* pin_w  = (const float*)d_in[3];
    const float* pout_w = (const float*)d_in[4];
    const float* b1_w   = (const float*)d_in[5];
    const float* b1_b   = (const float*)d_in[6];
    const float* b2_w   = (const float*)d_in[7];
    const float* b2_b   = (const float*)d_in[8];
    const float* tok_w  = (const float*)d_in[9];
    const float* tok_b  = (const float*)d_in[10];
    const float* dw_bias= (const float*)d_in[11];
    float* out = (float*)d_out;

    transpose_w<<<192, 256>>>(pin_w, pout_w);
    ln_kernel<<<dim3(P / 256, BT), 256>>>(x, ln_w, ln_b);
    pin_gemm<<<dim3(P / 128, 2, BT), 256>>>();
    pool_branch<<<BT * HID, 256>>>(b1_w, b1_b, b2_w, b2_b);
    kern_gemm<<<9, 128>>>(tok_w, tok_b);
    dyn_dw<<<dim3(BT * HID, 2), 256>>>(dw_bias);
    pout_gemm<<<dim3(P / 256, BT), 256>>>(out, x);
}

// round 3
// speedup vs baseline: 3.4596x; 3.4596x over previous
#include <cuda_runtime.h>
#include <cuda_bf16.h>
#include <cstdint>

// Problem constants
#define BT 16          // b*t
#define C_ 64          // dim
#define HID 128
#define P 16384        // H*W = 128*128
typedef __nv_bfloat16 bf16;

// ---------------- scratch (device globals; no runtime allocation) ------------
__device__ bf16  g_xnb[(size_t)BT * P * C_];     // layernormed x, bf16 [bt][p][c]
__device__ bf16  g_x1[(size_t)BT * HID * P];     // pin out ch 0..127, bf16 [bt][ch][p]
__device__ bf16  g_x2[(size_t)BT * HID * P];     // pin out ch 128..255
__device__ bf16  g_gated[(size_t)BT * HID * P];  // (dyn dwconv + bias) * x2, [bt][ch][p]
__device__ float g_pooled[BT * HID];
__device__ float g_kern[BT * HID * 9];
__device__ bf16  g_pinTb[3 * 256 * 64];          // [dt][n(256)][c(64)]
__device__ bf16  g_poutTb[3 * 64 * 128];         // [dt][n(64)][k(128)]

// ---------------- mma helpers -------------------------------------------------
__device__ __forceinline__ uint32_t smem_u32(const void* p) {
    return (uint32_t)__cvta_generic_to_shared(p);
}
__device__ __forceinline__ void ldm_x4(uint32_t& r0, uint32_t& r1, uint32_t& r2,
                                       uint32_t& r3, uint32_t addr) {
    asm volatile("ldmatrix.sync.aligned.m8n8.x4.shared.b16 {%0,%1,%2,%3}, [%4];"
                 : "=r"(r0), "=r"(r1), "=r"(r2), "=r"(r3) : "r"(addr));
}
__device__ __forceinline__ void ldm_x4t(uint32_t& r0, uint32_t& r1, uint32_t& r2,
                                        uint32_t& r3, uint32_t addr) {
    asm volatile("ldmatrix.sync.aligned.m8n8.x4.trans.shared.b16 {%0,%1,%2,%3}, [%4];"
                 : "=r"(r0), "=r"(r1), "=r"(r2), "=r"(r3) : "r"(addr));
}
__device__ __forceinline__ void mma16816(float* c, const uint32_t* a, const uint32_t* b) {
    asm volatile(
        "mma.sync.aligned.m16n8k16.row.col.f32.bf16.bf16.f32 "
        "{%0,%1,%2,%3}, {%4,%5,%6,%7}, {%8,%9}, {%0,%1,%2,%3};"
        : "+f"(c[0]), "+f"(c[1]), "+f"(c[2]), "+f"(c[3])
        : "r"(a[0]), "r"(a[1]), "r"(a[2]), "r"(a[3]), "r"(b[0]), "r"(b[1]));
}

// ---------------- K0: weight transpose + bf16 cast ---------------------------
__global__ void __launch_bounds__(256) transpose_w(const float* __restrict__ pin,
                                                   const float* __restrict__ pout) {
    int i = blockIdx.x * 256 + threadIdx.x;
    if (i < 3 * 256 * 64) {               // pinTb [dt][n][c]
        int c = i & 63;
        int n = (i >> 6) & 255;
        int dt = i >> 14;
        g_pinTb[i] = __float2bfloat16(pin[(n * 64 + c) * 3 + dt]);
    }
    if (i < 3 * 64 * 128) {               // poutTb [dt][n][k]
        int k = i & 127;
        int n = (i >> 7) & 63;
        int dt = i >> 13;
        g_poutTb[i] = __float2bfloat16(pout[(n * 128 + k) * 3 + dt]);
    }
}

// ---------------- K1: LayerNorm over channel dim per pixel -------------------
// writes bf16 [bt][p][c] rows (64 contiguous = 128B per pixel)
__global__ void __launch_bounds__(256) ln_kernel(const float* __restrict__ x,
                                                 const float* __restrict__ lw,
                                                 const float* __restrict__ lb) {
    int p = blockIdx.x * 256 + threadIdx.x;
    int bt = blockIdx.y;
    const float* xp = x + (size_t)bt * C_ * P + p;
    float v[64];
    float sum = 0.f;
#pragma unroll
    for (int c = 0; c < 64; c++) { v[c] = xp[(size_t)c * P]; sum += v[c]; }
    float mu = sum * (1.f / 64.f);
    float var = 0.f;
#pragma unroll
    for (int c = 0; c < 64; c++) { float d = v[c] - mu; var += d * d; }
    float rs = rsqrtf(var * (1.f / 64.f) + 1e-5f);
    bf16 ob[64];
#pragma unroll
    for (int c = 0; c < 64; c++)
        ob[c] = __float2bfloat16((v[c] - mu) * rs * lw[c] + lb[c]);
    uint4* dst = (uint4*)(g_xnb + ((size_t)bt * P + p) * 64);
#pragma unroll
    for (int i = 0; i < 8; i++) dst[i] = ((uint4*)ob)[i];
}

// ---------------- K2: pin conv3d GEMM, tensor cores --------------------------
// out[p, n] = sum_{dt,c} xn[bt+dt-1][p][c] * pinW[dt][n][c];  BM=128, BN=128
// 8 warps as 4(m) x 2(n): warp tile 32x64. K per tap = 64 (4 k16-steps).
__global__ void __launch_bounds__(256) pin_mma() {
    const int bt = blockIdx.z;
    const int t = bt & 7;
    const int p0 = blockIdx.x * 128;
    const int n0 = blockIdx.y * 128;
    __shared__ __align__(16) bf16 sh[2 * 128 * 72];      // As | Bs (36864 B)
    bf16* As = sh;                 // [128 p][72]
    bf16* Bs = sh + 128 * 72;      // [128 n][72]
    const int tid = threadIdx.x;
    const int wid = tid >> 5, l = tid & 31;
    const int wm = (wid & 3) * 32;
    const int wn = (wid >> 2) * 64;
    float acc[2][8][4];
#pragma unroll
    for (int i = 0; i < 2; i++)
#pragma unroll
        for (int j = 0; j < 8; j++)
#pragma unroll
            for (int k = 0; k < 4; k++) acc[i][j][k] = 0.f;

    const int lr = tid >> 3, lc = (tid & 7) * 8;   // gmem->smem copy coords
#pragma unroll 1
    for (int dt = 0; dt < 3; dt++) {
        const int ts = t + dt - 1;
        if (ts < 0 || ts > 7) continue;
        const bf16* ab = g_xnb + ((size_t)(bt + dt - 1) * P + p0) * 64;
        const bf16* wb = g_pinTb + (dt * 256 + n0) * 64;
#pragma unroll
        for (int ps = 0; ps < 4; ps++) {
            *(uint4*)&As[(lr + ps * 32) * 72 + lc] = *(const uint4*)&ab[(size_t)(lr + ps * 32) * 64 + lc];
            *(uint4*)&Bs[(lr + ps * 32) * 72 + lc] = *(const uint4*)&wb[(lr + ps * 32) * 64 + lc];
        }
        __syncthreads();
#pragma unroll
        for (int kk = 0; kk < 4; kk++) {
            const int k0 = kk * 16;
            uint32_t a[2][4];
#pragma unroll
            for (int mt = 0; mt < 2; mt++)
                ldm_x4(a[mt][0], a[mt][1], a[mt][2], a[mt][3],
                       smem_u32(&As[(wm + mt * 16 + (l & 15)) * 72 + k0 + (l >> 4) * 8]));
            uint32_t b[8][2];
#pragma unroll
            for (int nt2 = 0; nt2 < 4; nt2++) {
                uint32_t r0, r1, r2, r3;
                ldm_x4(r0, r1, r2, r3,
                       smem_u32(&Bs[(wn + nt2 * 16 + (l & 15)) * 72 + k0 + (l >> 4) * 8]));
                b[nt2 * 2][0] = r0; b[nt2 * 2][1] = r2;
                b[nt2 * 2 + 1][0] = r1; b[nt2 * 2 + 1][1] = r3;
            }
#pragma unroll
            for (int mt = 0; mt < 2; mt++)
#pragma unroll
                for (int nt = 0; nt < 8; nt++) mma16816(acc[mt][nt], a[mt], b[nt]);
        }
        __syncthreads();
    }
    // epilogue: stage bf16 [128 ch][136 p] in smem, then coalesced 16B stores
    bf16* st = sh;
#pragma unroll
    for (int mt = 0; mt < 2; mt++)
#pragma unroll
        for (int nt = 0; nt < 8; nt++)
#pragma unroll
            for (int j = 0; j < 4; j++) {
                int p = wm + mt * 16 + (l >> 2) + ((j >= 2) ? 8 : 0);
                int ch = wn + nt * 8 + (l & 3) * 2 + (j & 1);
                st[ch * 136 + p] = __float2bfloat16(acc[mt][nt][j]);
            }
    __syncthreads();
    bf16* base = ((n0 == 0) ? g_x1 : g_x2) + (size_t)bt * 128 * P;
#pragma unroll
    for (int ps = 0; ps < 8; ps++) {
        int n = (tid >> 4) + ps * 16;
        int p = (tid & 15) * 8;
        *(uint4*)&base[(size_t)n * P + p0 + p] = *(uint4*)&st[n * 136 + p];
    }
}

// ---------------- K3: fused pooling branch (bf16 input) ----------------------
__global__ void __launch_bounds__(256) pool_branch(const float* __restrict__ b1w,
                                                   const float* __restrict__ b1b,
                                                   const float* __restrict__ b2w,
                                                   const float* __restrict__ b2b) {
    __shared__ float sA[4096];
    __shared__ float sB[4096];
    __shared__ float red[8];
    const int btc = blockIdx.x;
    const int ch = btc & 127;
    const int tid = threadIdx.x;
    const bf16* src = g_x1 + (size_t)btc * P;

    for (int i = tid; i < 4096; i += 256) {
        int py = i >> 6, px = i & 63;
        __nv_bfloat162 a = ((const __nv_bfloat162*)(src + (py * 2) * 128))[px];
        __nv_bfloat162 b = ((const __nv_bfloat162*)(src + (py * 2 + 1) * 128))[px];
        sA[i] = 0.25f * (__bfloat162float(a.x) + __bfloat162float(a.y) +
                         __bfloat162float(b.x) + __bfloat162float(b.y));
    }
    __syncthreads();
    for (int it = 0; it < 3; it++) {
        float w[9];
#pragma unroll
        for (int k = 0; k < 9; k++) w[k] = b1w[(it * 128 + ch) * 9 + k];
        float bias = b1b[it * 128 + ch];
        const float* in = (it & 1) ? sB : sA;
        float* out = (it & 1) ? sA : sB;
        for (int i = tid; i < 4096; i += 256) {
            int y = i >> 6, x = i & 63;
            float acc = bias;
#pragma unroll
            for (int ky = 0; ky < 3; ky++) {
                int yy = y + ky - 1;
                if (yy < 0 || yy > 63) continue;
#pragma unroll
                for (int kx = 0; kx < 3; kx++) {
                    int xx = x + kx - 1;
                    if (xx < 0 || xx > 63) continue;
                    acc += in[yy * 64 + xx] * w[ky * 3 + kx];
                }
            }
            out[i] = acc;
        }
        __syncthreads();
    }
    for (int i = tid; i < 1024; i += 256) {
        int py = i >> 5, px = i & 31;
        float m0 = fmaxf(sB[(py * 2) * 64 + px * 2], sB[(py * 2) * 64 + px * 2 + 1]);
        float m1 = fmaxf(sB[(py * 2 + 1) * 64 + px * 2], sB[(py * 2 + 1) * 64 + px * 2 + 1]);
        sA[i] = fmaxf(m0, m1);
    }
    __syncthreads();
    for (int it = 0; it < 3; it++) {
        float w[9];
#pragma unroll
        for (int k = 0; k < 9; k++) w[k] = b2w[(it * 128 + ch) * 9 + k];
        float bias = b2b[it * 128 + ch];
        const float* in = (it & 1) ? sB : sA;
        float* out = (it & 1) ? sA : sB;
        for (int i = tid; i < 1024; i += 256) {
            int y = i >> 5, x = i & 31;
            float acc = bias;
#pragma unroll
            for (int ky = 0; ky < 3; ky++) {
                int yy = y + ky - 1;
                if (yy < 0 || yy > 31) continue;
#pragma unroll
                for (int kx = 0; kx < 3; kx++) {
                    int xx = x + kx - 1;
                    if (xx < 0 || xx > 31) continue;
                    acc += in[yy * 32 + xx] * w[ky * 3 + kx];
                }
            }
            out[i] = acc;
        }
        __syncthreads();
    }
    float s = 0.f;
    for (int i = tid; i < 1024; i += 256) s += sB[i];
#pragma unroll
    for (int o = 16; o; o >>= 1) s += __shfl_xor_sync(0xFFFFFFFFu, s, o);
    if ((tid & 31) == 0) red[tid >> 5] = s;
    __syncthreads();
    if (tid == 0) {
        float tot = 0.f;
#pragma unroll
        for (int i = 0; i < 8; i++) tot += red[i];
        g_pooled[btc] = tot * (1.f / 1024.f);
    }
}

// ---------------- K4: kern = pooled @ tok_w.T + tok_b ------------------------
__global__ void __launch_bounds__(128) kern_gemm(const float* __restrict__ tw,
                                                 const float* __restrict__ tb) {
    __shared__ float sp[2048];
    int tid = threadIdx.x;
    for (int i = tid; i < 2048; i += 128) sp[i] = g_pooled[i];
    __syncthreads();
    int j = blockIdx.x * 128 + tid;
    float acc[16];
#pragma unroll
    for (int b = 0; b < 16; b++) acc[b] = 0.f;
    const float4* wr = (const float4*)(tw + j * 128);
    for (int c4 = 0; c4 < 32; c4++) {
        float4 w = wr[c4];
#pragma unroll
        for (int b = 0; b < 16; b++) {
            const float* pp = sp + b * 128 + c4 * 4;
            acc[b] += w.x * pp[0] + w.y * pp[1] + w.z * pp[2] + w.w * pp[3];
        }
    }
    float bias = tb[j];
#pragma unroll
    for (int b = 0; b < 16; b++) g_kern[b * 1152 + j] = acc[b] + bias;
}

// ---------------- K5: dynamic depthwise conv + gate (bf16 io) ----------------
__global__ void __launch_bounds__(256) dyn_dw(const float* __restrict__ dwb) {
    __shared__ float s[66 * 128];
    const int btc = blockIdx.x;
    const int half = blockIdx.y;
    const int bt = btc >> 7, ch = btc & 127;
    const int r0 = half * 64;
    const int tid = threadIdx.x;
    const bf16* src = g_x1 + (size_t)btc * P;
    for (int i = tid; i < 66 * 128; i += 256) {
        int rr = (i >> 7) + r0 - 1;
        s[i] = (rr >= 0 && rr < 128) ? __bfloat162float(src[rr * 128 + (i & 127)]) : 0.f;
    }
    float kw[9];
#pragma unroll
    for (int k = 0; k < 9; k++) kw[k] = g_kern[bt * 1152 + ch * 9 + k];
    const float bias = dwb[ch];
    __syncthreads();
    const bf16* x2p = g_x2 + (size_t)btc * P + r0 * 128;
    bf16* dst = g_gated + (size_t)btc * P + r0 * 128;
    for (int i = tid; i < 64 * 128; i += 256) {
        int ly = (i >> 7) + 1;
        int x = i & 127;
        float acc = 0.f;
#pragma unroll
        for (int ky = 0; ky < 3; ky++) {
            const float* row = s + (ly + ky - 1) * 128;
            if (x > 0)   acc += row[x - 1] * kw[ky * 3];
                         acc += row[x]     * kw[ky * 3 + 1];
            if (x < 127) acc += row[x + 1] * kw[ky * 3 + 2];
        }
        dst[i] = __float2bfloat16((acc + bias) * __bfloat162float(x2p[i]));
    }
}

// ---------------- K6: pout conv3d GEMM + residual, tensor cores --------------
// out[p, n(64)] = sum_{dt,ch} gated[bt+dt-1][ch][p] * poutW[dt][n][ch]
// BM=128, BN=64; 8 warps 4(m) x 2(n): warp 32x32. A via ldmatrix.trans.
__global__ void __launch_bounds__(256) pout_mma(float* __restrict__ out,
                                                const float* __restrict__ x) {
    const int bt = blockIdx.y;
    const int t = bt & 7;
    const int p0 = blockIdx.x * 128;
    __shared__ __align__(16) unsigned char shraw[34816];
    bf16* As = (bf16*)shraw;                    // [64 ch][136 p]  17408 B
    bf16* Bs = (bf16*)(shraw + 17408);          // [64 n][72]      9216 B
    float* st = (float*)shraw;                  // [64 ch][132 p]  33792 B (epilogue)
    const int tid = threadIdx.x;
    const int wid = tid >> 5, l = tid & 31;
    const int wm = (wid & 3) * 32;
    const int wn = (wid >> 2) * 32;
    float acc[2][4][4];
#pragma unroll
    for (int i = 0; i < 2; i++)
#pragma unroll
        for (int j = 0; j < 4; j++)
#pragma unroll
            for (int k = 0; k < 4; k++) acc[i][j][k] = 0.f;

    const int ar = tid >> 4, ac = (tid & 15) * 8;   // A copy: 16 thr/row
    const int br = tid >> 3, bc = (tid & 7) * 8;    // B copy: 8 thr/row
#pragma unroll 1
    for (int dt = 0; dt < 3; dt++) {
        const int ts = t + dt - 1;
        if (ts < 0 || ts > 7) continue;
#pragma unroll 1
        for (int half = 0; half < 2; half++) {
            const int ch0 = half * 64;
            const bf16* ab = g_gated + ((size_t)((bt + dt - 1) * 128 + ch0)) * P + p0;
            const bf16* wb = g_poutTb + (dt * 64) * 128 + ch0;
#pragma unroll
            for (int ps = 0; ps < 4; ps++)
                *(uint4*)&As[(ar + ps * 16) * 136 + ac] =
                    *(const uint4*)&ab[(size_t)(ar + ps * 16) * P + ac];
#pragma unroll
            for (int ps = 0; ps < 2; ps++)
                *(uint4*)&Bs[(br + ps * 32) * 72 + bc] =
                    *(const uint4*)&wb[(br + ps * 32) * 128 + bc];
            __syncthreads();
#pragma unroll
            for (int kk = 0; kk < 4; kk++) {
                const int k0 = kk * 16;
                uint32_t a[2][4];
#pragma unroll
                for (int mt = 0; mt < 2; mt++) {
                    int row = k0 + (l & 7) + ((l >> 4) << 3);
                    int col = wm + mt * 16 + ((l >> 3) & 1) * 8;
                    ldm_x4t(a[mt][0], a[mt][1], a[mt][2], a[mt][3],
                            smem_u32(&As[row * 136 + col]));
                }
                uint32_t b[4][2];
#pragma unroll
                for (int nt2 = 0; nt2 < 2; nt2++) {
                    uint32_t r0, r1, r2, r3;
                    ldm_x4(r0, r1, r2, r3,
                           smem_u32(&Bs[(wn + nt2 * 16 + (l & 15)) * 72 + k0 + (l >> 4) * 8]));
                    b[nt2 * 2][0] = r0; b[nt2 * 2][1] = r2;
                    b[nt2 * 2 + 1][0] = r1; b[nt2 * 2 + 1][1] = r3;
                }
#pragma unroll
                for (int mt = 0; mt < 2; mt++)
#pragma unroll
                    for (int nt = 0; nt < 4; nt++) mma16816(acc[mt][nt], a[mt], b[nt]);
            }
            __syncthreads();
        }
    }
    // epilogue: stage fp32 [64 ch][132 p], then coalesced residual-add + store
#pragma unroll
    for (int mt = 0; mt < 2; mt++)
#pragma unroll
        for (int nt = 0; nt < 4; nt++)
#pragma unroll
            for (int j = 0; j < 4; j++) {
                int p = wm + mt * 16 + (l >> 2) + ((j >= 2) ? 8 : 0);
                int ch = wn + nt * 8 + (l & 3) * 2 + (j & 1);
                st[ch * 132 + p] = acc[mt][nt][j];
            }
    __syncthreads();
    const size_t base = (size_t)bt * 64 * P + p0;
#pragma unroll
    for (int ps = 0; ps < 8; ps++) {
        int ch = (tid >> 5) + ps * 8;
        int p = (tid & 31) * 4;
        float4 v = *(float4*)&st[ch * 132 + p];
        float4 xr = *(const float4*)&x[base + (size_t)ch * P + p];
        v.x += xr.x; v.y += xr.y; v.z += xr.z; v.w += xr.w;
        *(float4*)&out[base + (size_t)ch * P + p] = v;
    }
}

// ---------------- launch ------------------------------------------------------
extern "C" void kernel_launch(void* const* d_in, const int* in_sizes, int n_in,
                              void* d_out, int out_size) {
    (void)in_sizes; (void)n_in; (void)out_size;
    const float* x      = (const float*)d_in[0];
    const float* ln_w   = (const float*)d_in[1];
    const float* ln_b   = (const float*)d_in[2];
    const float* pin_w  = (const float*)d_in[3];
    const float* pout_w = (const float*)d_in[4];
    const float* b1_w   = (const float*)d_in[5];
    const float* b1_b   = (const float*)d_in[6];
    const float* b2_w   = (const float*)d_in[7];
    const float* b2_b   = (const float*)d_in[8];
    const float* tok_w  = (const float*)d_in[9];
    const float* tok_b  = (const float*)d_in[10];
    const float* dw_bias= (const float*)d_in[11];
    float* out = (float*)d_out;

    transpose_w<<<192, 256>>>(pin_w, pout_w);
    ln_kernel<<<dim3(P / 256, BT), 256>>>(x, ln_w, ln_b);
    pin_mma<<<dim3(P / 128, 2, BT), 256>>>();
    pool_branch<<<BT * HID, 256>>>(b1_w, b1_b, b2_w, b2_b);
    kern_gemm<<<9, 128>>>(tok_w, tok_b);
    dyn_dw<<<dim3(BT * HID, 2), 256>>>(dw_bias);
    pout_mma<<<dim3(P / 128, BT), 256>>>(out, x);
}

// round 4
// speedup vs baseline: 4.0850x; 1.1808x over previous
#include <cuda_runtime.h>
#include <cuda_bf16.h>
#include <cstdint>

// Problem constants
#define BT 16          // b*t
#define C_ 64          // dim
#define HID 128
#define P 16384        // H*W = 128*128
typedef __nv_bfloat16 bf16;

// ---------------- scratch (device globals; no runtime allocation) ------------
__device__ bf16  g_xnb[(size_t)BT * P * C_];     // layernormed x, bf16 [bt][p][c]
__device__ bf16  g_x1[(size_t)BT * HID * P];     // pin out ch 0..127, bf16 [bt][ch][p]
__device__ bf16  g_x2[(size_t)BT * HID * P];     // pin out ch 128..255
__device__ bf16  g_gated[(size_t)BT * HID * P];  // (dyn dwconv + bias) * x2, [bt][ch][p]
__device__ float g_pooled[BT * HID];
__device__ float g_kern[BT * HID * 9];
__device__ bf16  g_pinTb[3 * 256 * 64];          // [dt][n(256)][c(64)]
__device__ bf16  g_poutTb[3 * 64 * 128];         // [dt][n(64)][k(128)]

// ---------------- mma helpers -------------------------------------------------
__device__ __forceinline__ uint32_t smem_u32(const void* p) {
    return (uint32_t)__cvta_generic_to_shared(p);
}
__device__ __forceinline__ void ldm_x4(uint32_t& r0, uint32_t& r1, uint32_t& r2,
                                       uint32_t& r3, uint32_t addr) {
    asm volatile("ldmatrix.sync.aligned.m8n8.x4.shared.b16 {%0,%1,%2,%3}, [%4];"
                 : "=r"(r0), "=r"(r1), "=r"(r2), "=r"(r3) : "r"(addr));
}
__device__ __forceinline__ void ldm_x4t(uint32_t& r0, uint32_t& r1, uint32_t& r2,
                                        uint32_t& r3, uint32_t addr) {
    asm volatile("ldmatrix.sync.aligned.m8n8.x4.trans.shared.b16 {%0,%1,%2,%3}, [%4];"
                 : "=r"(r0), "=r"(r1), "=r"(r2), "=r"(r3) : "r"(addr));
}
__device__ __forceinline__ void mma16816(float* c, const uint32_t* a, const uint32_t* b) {
    asm volatile(
        "mma.sync.aligned.m16n8k16.row.col.f32.bf16.bf16.f32 "
        "{%0,%1,%2,%3}, {%4,%5,%6,%7}, {%8,%9}, {%0,%1,%2,%3};"
        : "+f"(c[0]), "+f"(c[1]), "+f"(c[2]), "+f"(c[3])
        : "r"(a[0]), "r"(a[1]), "r"(a[2]), "r"(a[3]), "r"(b[0]), "r"(b[1]));
}

// ---------------- K0: weight transpose + bf16 cast ---------------------------
__global__ void __launch_bounds__(256) transpose_w(const float* __restrict__ pin,
                                                   const float* __restrict__ pout) {
    int i = blockIdx.x * 256 + threadIdx.x;
    if (i < 3 * 256 * 64) {               // pinTb [dt][n][c]
        int c = i & 63;
        int n = (i >> 6) & 255;
        int dt = i >> 14;
        g_pinTb[i] = __float2bfloat16(pin[(n * 64 + c) * 3 + dt]);
    }
    if (i < 3 * 64 * 128) {               // poutTb [dt][n][k]
        int k = i & 127;
        int n = (i >> 7) & 63;
        int dt = i >> 13;
        g_poutTb[i] = __float2bfloat16(pout[(n * 128 + k) * 3 + dt]);
    }
}

// ---------------- K1: LayerNorm over channel dim per pixel -------------------
__global__ void __launch_bounds__(256) ln_kernel(const float* __restrict__ x,
                                                 const float* __restrict__ lw,
                                                 const float* __restrict__ lb) {
    int p = blockIdx.x * 256 + threadIdx.x;
    int bt = blockIdx.y;
    const float* xp = x + (size_t)bt * C_ * P + p;
    float v[64];
    float sum = 0.f;
#pragma unroll
    for (int c = 0; c < 64; c++) { v[c] = xp[(size_t)c * P]; sum += v[c]; }
    float mu = sum * (1.f / 64.f);
    float var = 0.f;
#pragma unroll
    for (int c = 0; c < 64; c++) { float d = v[c] - mu; var += d * d; }
    float rs = rsqrtf(var * (1.f / 64.f) + 1e-5f);
    bf16 ob[64];
#pragma unroll
    for (int c = 0; c < 64; c++)
        ob[c] = __float2bfloat16((v[c] - mu) * rs * lw[c] + lb[c]);
    uint4* dst = (uint4*)(g_xnb + ((size_t)bt * P + p) * 64);
#pragma unroll
    for (int i = 0; i < 8; i++) dst[i] = ((uint4*)ob)[i];
}

// ---------------- K2: pin conv3d GEMM, tensor cores --------------------------
__global__ void __launch_bounds__(256) pin_mma() {
    const int bt = blockIdx.z;
    const int t = bt & 7;
    const int p0 = blockIdx.x * 128;
    const int n0 = blockIdx.y * 128;
    __shared__ __align__(16) bf16 sh[2 * 128 * 72];      // As | Bs (36864 B)
    bf16* As = sh;                 // [128 p][72]
    bf16* Bs = sh + 128 * 72;      // [128 n][72]
    const int tid = threadIdx.x;
    const int wid = tid >> 5, l = tid & 31;
    const int wm = (wid & 3) * 32;
    const int wn = (wid >> 2) * 64;
    float acc[2][8][4];
#pragma unroll
    for (int i = 0; i < 2; i++)
#pragma unroll
        for (int j = 0; j < 8; j++)
#pragma unroll
            for (int k = 0; k < 4; k++) acc[i][j][k] = 0.f;

    const int lr = tid >> 3, lc = (tid & 7) * 8;
#pragma unroll 1
    for (int dt = 0; dt < 3; dt++) {
        const int ts = t + dt - 1;
        if (ts < 0 || ts > 7) continue;
        const bf16* ab = g_xnb + ((size_t)(bt + dt - 1) * P + p0) * 64;
        const bf16* wb = g_pinTb + (dt * 256 + n0) * 64;
#pragma unroll
        for (int ps = 0; ps < 4; ps++) {
            *(uint4*)&As[(lr + ps * 32) * 72 + lc] = *(const uint4*)&ab[(size_t)(lr + ps * 32) * 64 + lc];
            *(uint4*)&Bs[(lr + ps * 32) * 72 + lc] = *(const uint4*)&wb[(lr + ps * 32) * 64 + lc];
        }
        __syncthreads();
#pragma unroll
        for (int kk = 0; kk < 4; kk++) {
            const int k0 = kk * 16;
            uint32_t a[2][4];
#pragma unroll
            for (int mt = 0; mt < 2; mt++)
                ldm_x4(a[mt][0], a[mt][1], a[mt][2], a[mt][3],
                       smem_u32(&As[(wm + mt * 16 + (l & 15)) * 72 + k0 + (l >> 4) * 8]));
            uint32_t b[8][2];
#pragma unroll
            for (int nt2 = 0; nt2 < 4; nt2++) {
                uint32_t r0, r1, r2, r3;
                ldm_x4(r0, r1, r2, r3,
                       smem_u32(&Bs[(wn + nt2 * 16 + (l & 15)) * 72 + k0 + (l >> 4) * 8]));
                b[nt2 * 2][0] = r0; b[nt2 * 2][1] = r2;
                b[nt2 * 2 + 1][0] = r1; b[nt2 * 2 + 1][1] = r3;
            }
#pragma unroll
            for (int mt = 0; mt < 2; mt++)
#pragma unroll
                for (int nt = 0; nt < 8; nt++) mma16816(acc[mt][nt], a[mt], b[nt]);
        }
        __syncthreads();
    }
    bf16* st = sh;
#pragma unroll
    for (int mt = 0; mt < 2; mt++)
#pragma unroll
        for (int nt = 0; nt < 8; nt++)
#pragma unroll
            for (int j = 0; j < 4; j++) {
                int p = wm + mt * 16 + (l >> 2) + ((j >= 2) ? 8 : 0);
                int ch = wn + nt * 8 + (l & 3) * 2 + (j & 1);
                st[ch * 136 + p] = __float2bfloat16(acc[mt][nt][j]);
            }
    __syncthreads();
    bf16* base = ((n0 == 0) ? g_x1 : g_x2) + (size_t)bt * 128 * P;
#pragma unroll
    for (int ps = 0; ps < 8; ps++) {
        int n = (tid >> 4) + ps * 16;
        int p = (tid & 15) * 8;
        *(uint4*)&base[(size_t)n * P + p0 + p] = *(uint4*)&st[n * 136 + p];
    }
}

// ---------------- K3: fused pooling branch — padded smem, branch-free --------
// stage1: padded 66x66 (stride 66), stage2: padded 34x34 (stride 34)
__global__ void __launch_bounds__(256) pool_branch(const float* __restrict__ b1w,
                                                   const float* __restrict__ b1b,
                                                   const float* __restrict__ b2w,
                                                   const float* __restrict__ b2b) {
    __shared__ float sA[66 * 66];
    __shared__ float sB[66 * 66];
    __shared__ float red[8];
    const int btc = blockIdx.x;
    const int ch = btc & 127;
    const int tid = threadIdx.x;
    const bf16* src = g_x1 + (size_t)btc * P;

    // zero halos of both 66-stride buffers (interiors overwritten each pass)
    for (int i = tid; i < 66; i += 256) {
        sA[i] = 0.f; sA[65 * 66 + i] = 0.f; sA[i * 66] = 0.f; sA[i * 66 + 65] = 0.f;
        sB[i] = 0.f; sB[65 * 66 + i] = 0.f; sB[i * 66] = 0.f; sB[i * 66 + 65] = 0.f;
    }
    // avgpool 128x128 -> 64x64 into sA interior
    for (int i = tid; i < 4096; i += 256) {
        int y = i >> 6, x = i & 63;
        __nv_bfloat162 a = ((const __nv_bfloat162*)(src + (y * 2) * 128))[x];
        __nv_bfloat162 b = ((const __nv_bfloat162*)(src + (y * 2 + 1) * 128))[x];
        sA[(y + 1) * 66 + x + 1] = 0.25f * (__bfloat162float(a.x) + __bfloat162float(a.y) +
                                            __bfloat162float(b.x) + __bfloat162float(b.y));
    }
    __syncthreads();

    // stage 1: 3x dwconv 3x3 @64x64, branch-free
    const int x1c = tid & 63;
    const int y1s = (tid >> 6) * 16;      // 4 strips x 16 rows
    for (int it = 0; it < 3; it++) {
        float w[9];
#pragma unroll
        for (int k = 0; k < 9; k++) w[k] = b1w[(it * 128 + ch) * 9 + k];
        const float bias = b1b[it * 128 + ch];
        const float* in = (it & 1) ? sB : sA;
        float* out = (it & 1) ? sA : sB;
#pragma unroll
        for (int yy = 0; yy < 16; yy++) {
            int y = y1s + yy;
            const float* r = in + y * 66 + x1c;
            float acc = bias
                + r[0]   * w[0] + r[1]   * w[1] + r[2]   * w[2]
                + r[66]  * w[3] + r[67]  * w[4] + r[68]  * w[5]
                + r[132] * w[6] + r[133] * w[7] + r[134] * w[8];
            out[(y + 1) * 66 + x1c + 1] = acc;
        }
        __syncthreads();
    }
    // result in sB66; maxpool 64->32 into sA34 (sA66 dead) + zero sA34 halos
    for (int i = tid; i < 34; i += 256) {
        sA[i] = 0.f; sA[33 * 34 + i] = 0.f; sA[i * 34] = 0.f; sA[i * 34 + 33] = 0.f;
    }
    for (int i = tid; i < 1024; i += 256) {
        int py = i >> 5, px = i & 31;
        const float* b0 = sB + (2 * py + 1) * 66 + 2 * px + 1;
        float m = fmaxf(fmaxf(b0[0], b0[1]), fmaxf(b0[66], b0[67]));
        sA[(py + 1) * 34 + px + 1] = m;
    }
    __syncthreads();

    // stage 2: 3x dwconv 3x3 @32x32 (zero sB34 halos during iter0: sB66 dead then)
    const int x2c = tid & 31;
    const int y2s = (tid >> 5) * 4;       // 8 strips x 4 rows
    for (int it = 0; it < 3; it++) {
        if (it == 0) {
            for (int i = tid; i < 34; i += 256) {
                sB[i] = 0.f; sB[33 * 34 + i] = 0.f; sB[i * 34] = 0.f; sB[i * 34 + 33] = 0.f;
            }
        }
        float w[9];
#pragma unroll
        for (int k = 0; k < 9; k++) w[k] = b2w[(it * 128 + ch) * 9 + k];
        const float bias = b2b[it * 128 + ch];
        const float* in = (it & 1) ? sB : sA;
        float* out = (it & 1) ? sA : sB;
#pragma unroll
        for (int yy = 0; yy < 4; yy++) {
            int y = y2s + yy;
            const float* r = in + y * 34 + x2c;
            float acc = bias
                + r[0]  * w[0] + r[1]  * w[1] + r[2]  * w[2]
                + r[34] * w[3] + r[35] * w[4] + r[36] * w[5]
                + r[68] * w[6] + r[69] * w[7] + r[70] * w[8];
            out[(y + 1) * 34 + x2c + 1] = acc;
        }
        __syncthreads();
    }
    // final in sB34 interior; spatial mean
    float s = 0.f;
    for (int i = tid; i < 1024; i += 256)
        s += sB[((i >> 5) + 1) * 34 + (i & 31) + 1];
#pragma unroll
    for (int o = 16; o; o >>= 1) s += __shfl_xor_sync(0xFFFFFFFFu, s, o);
    if ((tid & 31) == 0) red[tid >> 5] = s;
    __syncthreads();
    if (tid == 0) {
        float tot = 0.f;
#pragma unroll
        for (int i = 0; i < 8; i++) tot += red[i];
        g_pooled[btc] = tot * (1.f / 1024.f);
    }
}

// ---------------- K4: kern = pooled @ tok_w.T + tok_b ------------------------
__global__ void __launch_bounds__(128) kern_gemm(const float* __restrict__ tw,
                                                 const float* __restrict__ tb) {
    __shared__ float sp[2048];
    int tid = threadIdx.x;
    for (int i = tid; i < 2048; i += 128) sp[i] = g_pooled[i];
    __syncthreads();
    int j = blockIdx.x * 128 + tid;
    float acc[16];
#pragma unroll
    for (int b = 0; b < 16; b++) acc[b] = 0.f;
    const float4* wr = (const float4*)(tw + j * 128);
    for (int c4 = 0; c4 < 32; c4++) {
        float4 w = wr[c4];
#pragma unroll
        for (int b = 0; b < 16; b++) {
            const float* pp = sp + b * 128 + c4 * 4;
            acc[b] += w.x * pp[0] + w.y * pp[1] + w.z * pp[2] + w.w * pp[3];
        }
    }
    float bias = tb[j];
#pragma unroll
    for (int b = 0; b < 16; b++) g_kern[b * 1152 + j] = acc[b] + bias;
}

// ---------------- K5: dynamic depthwise conv + gate (vectorized) -------------
// padded smem [66][130] (zero cols 0/129), 2 outputs/thread, bf16x2 io
__global__ void __launch_bounds__(256) dyn_dw(const float* __restrict__ dwb) {
    __shared__ float s[66 * 130];
    const int btc = blockIdx.x;
    const int half = blockIdx.y;
    const int bt = btc >> 7, ch = btc & 127;
    const int r0 = half * 64;
    const int tid = threadIdx.x;
    const bf16* src = g_x1 + (size_t)btc * P;
    // zero padded columns
    for (int r = tid; r < 66; r += 256) { s[r * 130] = 0.f; s[r * 130 + 129] = 0.f; }
    // load 66 rows x 128 cols as 8-bf16 chunks
    for (int i = tid; i < 1056; i += 256) {
        int row = i >> 4, xc = (i & 15) * 8;
        int rr = row + r0 - 1;
        float v[8];
        if (rr >= 0 && rr < 128) {
            uint4 u = *(const uint4*)(src + rr * 128 + xc);
            const bf16* pb = (const bf16*)&u;
#pragma unroll
            for (int k = 0; k < 8; k++) v[k] = __bfloat162float(pb[k]);
        } else {
#pragma unroll
            for (int k = 0; k < 8; k++) v[k] = 0.f;
        }
#pragma unroll
        for (int k = 0; k < 8; k++) s[row * 130 + xc + 1 + k] = v[k];
    }
    float kw[9];
#pragma unroll
    for (int k = 0; k < 9; k++) kw[k] = g_kern[bt * 1152 + ch * 9 + k];
    const float bias = dwb[ch];
    __syncthreads();
    const bf16* x2p = g_x2 + (size_t)btc * P + r0 * 128;
    bf16* dst = g_gated + (size_t)btc * P + r0 * 128;
    for (int i = tid; i < 4096; i += 256) {       // 64 rows x 64 x-pairs
        int y = i >> 6;
        int xp = (i & 63) * 2;                     // output x = xp, xp+1
        const float* r = s + y * 130 + xp;         // padded col xp == x-1 of output xp
        float2 a0 = *(const float2*)(r);           // cols xp, xp+1
        float2 a1 = *(const float2*)(r + 2);       // cols xp+2, xp+3
        float2 b0 = *(const float2*)(r + 130);
        float2 b1 = *(const float2*)(r + 132);
        float2 c0 = *(const float2*)(r + 260);
        float2 c1 = *(const float2*)(r + 262);
        float o0 = a0.x * kw[0] + a0.y * kw[1] + a1.x * kw[2]
                 + b0.x * kw[3] + b0.y * kw[4] + b1.x * kw[5]
                 + c0.x * kw[6] + c0.y * kw[7] + c1.x * kw[8] + bias;
        float o1 = a0.y * kw[0] + a1.x * kw[1] + a1.y * kw[2]
                 + b0.y * kw[3] + b1.x * kw[4] + b1.y * kw[5]
                 + c0.y * kw[6] + c1.x * kw[7] + c1.y * kw[8] + bias;
        __nv_bfloat162 g2 = ((const __nv_bfloat162*)(x2p + y * 128))[xp >> 1];
        ((__nv_bfloat162*)(dst + y * 128))[xp >> 1] =
            __floats2bfloat162_rn(o0 * __bfloat162float(g2.x),
                                  o1 * __bfloat162float(g2.y));
    }
}

// ---------------- K6: pout conv3d GEMM + residual, tensor cores --------------
__global__ void __launch_bounds__(256) pout_mma(float* __restrict__ out,
                                                const float* __restrict__ x) {
    const int bt = blockIdx.y;
    const int t = bt & 7;
    const int p0 = blockIdx.x * 128;
    __shared__ __align__(16) unsigned char shraw[34816];
    bf16* As = (bf16*)shraw;                    // [64 ch][136 p]
    bf16* Bs = (bf16*)(shraw + 17408);          // [64 n][72]
    float* st = (float*)shraw;                  // [64 ch][132 p] (epilogue)
    const int tid = threadIdx.x;
    const int wid = tid >> 5, l = tid & 31;
    const int wm = (wid & 3) * 32;
    const int wn = (wid >> 2) * 32;
    float acc[2][4][4];
#pragma unroll
    for (int i = 0; i < 2; i++)
#pragma unroll
        for (int j = 0; j < 4; j++)
#pragma unroll
            for (int k = 0; k < 4; k++) acc[i][j][k] = 0.f;

    const int ar = tid >> 4, ac = (tid & 15) * 8;
    const int br = tid >> 3, bc = (tid & 7) * 8;
#pragma unroll 1
    for (int dt = 0; dt < 3; dt++) {
        const int ts = t + dt - 1;
        if (ts < 0 || ts > 7) continue;
#pragma unroll 1
        for (int half = 0; half < 2; half++) {
            const int ch0 = half * 64;
            const bf16* ab = g_gated + ((size_t)((bt + dt - 1) * 128 + ch0)) * P + p0;
            const bf16* wb = g_poutTb + (dt * 64) * 128 + ch0;
#pragma unroll
            for (int ps = 0; ps < 4; ps++)
                *(uint4*)&As[(ar + ps * 16) * 136 + ac] =
                    *(const uint4*)&ab[(size_t)(ar + ps * 16) * P + ac];
#pragma unroll
            for (int ps = 0; ps < 2; ps++)
                *(uint4*)&Bs[(br + ps * 32) * 72 + bc] =
                    *(const uint4*)&wb[(br + ps * 32) * 128 + bc];
            __syncthreads();
#pragma unroll
            for (int kk = 0; kk < 4; kk++) {
                const int k0 = kk * 16;
                uint32_t a[2][4];
#pragma unroll
                for (int mt = 0; mt < 2; mt++) {
                    int row = k0 + (l & 7) + ((l >> 4) << 3);
                    int col = wm + mt * 16 + ((l >> 3) & 1) * 8;
                    ldm_x4t(a[mt][0], a[mt][1], a[mt][2], a[mt][3],
                            smem_u32(&As[row * 136 + col]));
                }
                uint32_t b[4][2];
#pragma unroll
                for (int nt2 = 0; nt2 < 2; nt2++) {
                    uint32_t r0, r1, r2, r3;
                    ldm_x4(r0, r1, r2, r3,
                           smem_u32(&Bs[(wn + nt2 * 16 + (l & 15)) * 72 + k0 + (l >> 4) * 8]));
                    b[nt2 * 2][0] = r0; b[nt2 * 2][1] = r2;
                    b[nt2 * 2 + 1][0] = r1; b[nt2 * 2 + 1][1] = r3;
                }
#pragma unroll
                for (int mt = 0; mt < 2; mt++)
#pragma unroll
                    for (int nt = 0; nt < 4; nt++) mma16816(acc[mt][nt], a[mt], b[nt]);
            }
            __syncthreads();
        }
    }
#pragma unroll
    for (int mt = 0; mt < 2; mt++)
#pragma unroll
        for (int nt = 0; nt < 4; nt++)
#pragma unroll
            for (int j = 0; j < 4; j++) {
                int p = wm + mt * 16 + (l >> 2) + ((j >= 2) ? 8 : 0);
                int ch = wn + nt * 8 + (l & 3) * 2 + (j & 1);
                st[ch * 132 + p] = acc[mt][nt][j];
            }
    __syncthreads();
    const size_t base = (size_t)bt * 64 * P + p0;
#pragma unroll
    for (int ps = 0; ps < 8; ps++) {
        int ch = (tid >> 5) + ps * 8;
        int p = (tid & 31) * 4;
        float4 v = *(float4*)&st[ch * 132 + p];
        float4 xr = *(const float4*)&x[base + (size_t)ch * P + p];
        v.x += xr.x; v.y += xr.y; v.z += xr.z; v.w += xr.w;
        *(float4*)&out[base + (size_t)ch * P + p] = v;
    }
}

// ---------------- launch ------------------------------------------------------
extern "C" void kernel_launch(void* const* d_in, const int* in_sizes, int n_in,
                              void* d_out, int out_size) {
    (void)in_sizes; (void)n_in; (void)out_size;
    const float* x      = (const float*)d_in[0];
    const float* ln_w   = (const float*)d_in[1];
    const float* ln_b   = (const float*)d_in[2];
    const float* pin_w  = (const float*)d_in[3];
    const float* pout_w = (const float*)d_in[4];
    const float* b1_w   = (const float*)d_in[5];
    const float* b1_b   = (const float*)d_in[6];
    const float* b2_w   = (const float*)d_in[7];
    const float* b2_b   = (const float*)d_in[8];
    const float* tok_w  = (const float*)d_in[9];
    const float* tok_b  = (const float*)d_in[10];
    const float* dw_bias= (const float*)d_in[11];
    float* out = (float*)d_out;

    transpose_w<<<192, 256>>>(pin_w, pout_w);
    ln_kernel<<<dim3(P / 256, BT), 256>>>(x, ln_w, ln_b);
    pin_mma<<<dim3(P / 128, 2, BT), 256>>>();
    pool_branch<<<BT * HID, 256>>>(b1_w, b1_b, b2_w, b2_b);
    kern_gemm<<<9, 128>>>(tok_w, tok_b);
    dyn_dw<<<dim3(BT * HID, 2), 256>>>(dw_bias);
    pout_mma<<<dim3(P / 128, BT), 256>>>(out, x);
}